// round 13
// baseline (speedup 1.0000x reference)
#include <cuda_runtime.h>
#include <cstdint>

// Problem constants
#define B   8
#define T   2048
#define C   256
#define L   32
#define DQ  512
#define WSZ 32
#define NCH 8
#define CIC 4
#define NW  2017      // T - WSZ + 1
#define NS  2045      // T - CIC + 1
#define DSPLIT 16     // d-split for enc partial GEMM

// ---------------- scratch (device globals; no allocs allowed) ----------------
__device__ float g_part1[DSPLIT * B * L * C];   // 4 MB
__device__ float g_part2[DSPLIT * B * L * C];   // 4 MB
__device__ float g_enc1[B * L * C];             // 256 KB
__device__ float g_enc2[B * L * C];             // 256 KB (pre-scaled by 0.25)
__device__ int   g_labels[B * T];               // 64 KB

// majority of 4 labels; tie -> smallest label (== argmax-first over counts)
__device__ __forceinline__ int maj4(int a0, int a1, int a2, int a3) {
    int la[4] = {a0, a1, a2, a3};
    int bc = 0, bl = L;
#pragma unroll
    for (int i = 0; i < 4; i++) {
        int cnt = (la[0] == la[i]) + (la[1] == la[i]) +
                  (la[2] == la[i]) + (la[3] == la[i]);
        if (cnt > bc || (cnt == bc && la[i] < bl)) { bc = cnt; bl = la[i]; }
    }
    return bl;
}

// ---------------------------------------------------------------------------
// K1a: partial enc GEMMs.  enc{1,2}[b,l,c] = sum_d query[b,l,d]*W{1,2}[d,c]
// grid (DSPLIT, B), 256 threads.
// ---------------------------------------------------------------------------
__global__ void k_enc_partial(const float* __restrict__ query,
                              const float* __restrict__ W1,
                              const float* __restrict__ W2) {
    __shared__ float q_s[L * 32];   // [l][dd]
    const int b  = blockIdx.y;
    const int dc = blockIdx.x;
    const int d0 = dc * 32;

    for (int i = threadIdx.x; i < L * 32; i += 256) {
        int l = i >> 5, dd = i & 31;
        q_s[i] = query[((b * L + l) * DQ) + d0 + dd];
    }
    __syncthreads();

    const int warp = threadIdx.x >> 5, lane = threadIdx.x & 31;

    float4 a1[4][2], a2[4][2];
#pragma unroll
    for (int i = 0; i < 4; i++)
#pragma unroll
        for (int p = 0; p < 2; p++) {
            a1[i][p] = make_float4(0.f, 0.f, 0.f, 0.f);
            a2[i][p] = make_float4(0.f, 0.f, 0.f, 0.f);
        }

    for (int dd = 0; dd < 32; dd++) {
        const int d = d0 + dd;
        const float4* w1r = (const float4*)(W1 + d * C);
        const float4* w2r = (const float4*)(W2 + d * C);
        float4 w1a = w1r[lane], w1b = w1r[lane + 32];
        float4 w2a = w2r[lane], w2b = w2r[lane + 32];
#pragma unroll
        for (int i = 0; i < 4; i++) {
            float q = q_s[(warp * 4 + i) * 32 + dd];
            a1[i][0].x += q * w1a.x; a1[i][0].y += q * w1a.y;
            a1[i][0].z += q * w1a.z; a1[i][0].w += q * w1a.w;
            a1[i][1].x += q * w1b.x; a1[i][1].y += q * w1b.y;
            a1[i][1].z += q * w1b.z; a1[i][1].w += q * w1b.w;
            a2[i][0].x += q * w2a.x; a2[i][0].y += q * w2a.y;
            a2[i][0].z += q * w2a.z; a2[i][0].w += q * w2a.w;
            a2[i][1].x += q * w2b.x; a2[i][1].y += q * w2b.y;
            a2[i][1].z += q * w2b.z; a2[i][1].w += q * w2b.w;
        }
    }

#pragma unroll
    for (int i = 0; i < 4; i++) {
        int l = warp * 4 + i;
        float4* p1 = (float4*)(g_part1 + (((size_t)dc * B + b) * L + l) * C);
        float4* p2 = (float4*)(g_part2 + (((size_t)dc * B + b) * L + l) * C);
        p1[lane] = a1[i][0]; p1[lane + 32] = a1[i][1];
        p2[lane] = a2[i][0]; p2[lane + 32] = a2[i][1];
    }
}

// K1b: reduce d-split partials + bias. grid (B*L), 256 threads (thread = c).
// NOTE: g_enc2 is pre-scaled by 0.25 (the mean4 divisor) — exact pow2 scale.
__global__ void k_enc_reduce(const float* __restrict__ b1,
                             const float* __restrict__ b2) {
    const int b = blockIdx.x >> 5, l = blockIdx.x & 31, c = threadIdx.x;
    float s1 = 0.f, s2 = 0.f;
#pragma unroll
    for (int dc = 0; dc < DSPLIT; dc++) {
        size_t idx = (((size_t)dc * B + b) * L + l) * C + c;
        s1 += g_part1[idx];
        s2 += g_part2[idx];
    }
    g_enc1[(b * L + l) * C + c] = s1 + b1[c];
    g_enc2[(b * L + l) * C + c] = 0.25f * (s2 + b2[c]);
}

// ---------------------------------------------------------------------------
// K2 (GEMM-tiled, scalar FFMA, 256 threads):
// sim[t,l] = sum_c vis[b,t,c]*enc1[b,l,c];  labels[b,t] = argmax_l (first max).
// Block = 256 thr, tile 64t x 32l; thread = 2t x 4l (8 accumulators).
// enc1 staged transposed [c][l] (stride 36 -> conflict-free LDS.128 over l);
// vis staged [t][c] stride 65 (broadcast scalar LDS).
// grid (T/64, B) = 256 blocks, 2048 warps (~14/SM).
// ---------------------------------------------------------------------------
#define VP 65
#define EP 36
__global__ void __launch_bounds__(256)
k_labels(const float* __restrict__ vis) {
    __shared__ float vis_s[64 * VP];    // 16.6 KB
    __shared__ float enc_s[64 * EP];    //  9.2 KB
    __shared__ float sim_s[64 * 33];    //  8.4 KB

    const int b  = blockIdx.y;
    const int t0 = blockIdx.x * 64;
    const int tid = threadIdx.x;
    const int ti = tid >> 3;          // 0..31 -> t rows ti*2, ti*2+1
    const int li = (tid & 7) * 4;     // 0,4,...,28

    float acc0[4], acc1[4];
#pragma unroll
    for (int j = 0; j < 4; j++) { acc0[j] = 0.f; acc1[j] = 0.f; }

    for (int ch = 0; ch < 4; ch++) {
        // stage vis rows t0..+63, cols ch*64..+63 (1024 float4 slots)
#pragma unroll
        for (int k = 0; k < 4; k++) {
            int slot = tid + k * 256;
            int r = slot >> 4, c4 = slot & 15;
            float4 vv = *((const float4*)(vis + ((size_t)(b * T + t0 + r)) * C + ch * 64) + c4);
            float* dst = vis_s + r * VP + c4 * 4;
            dst[0] = vv.x; dst[1] = vv.y; dst[2] = vv.z; dst[3] = vv.w;
        }
        // stage enc1 transposed [c][l] (512 float4 slots)
#pragma unroll
        for (int k = 0; k < 2; k++) {
            int slot = tid + k * 256;
            int l = slot >> 4, c4 = slot & 15;
            float4 ev = *((const float4*)(g_enc1 + (size_t)(b * L + l) * C + ch * 64) + c4);
            enc_s[(c4 * 4 + 0) * EP + l] = ev.x;
            enc_s[(c4 * 4 + 1) * EP + l] = ev.y;
            enc_s[(c4 * 4 + 2) * EP + l] = ev.z;
            enc_s[(c4 * 4 + 3) * EP + l] = ev.w;
        }
        __syncthreads();

        const float* v0p = vis_s + (ti * 2 + 0) * VP;
        const float* v1p = vis_s + (ti * 2 + 1) * VP;
        const float* ep  = enc_s + li;
#pragma unroll 4
        for (int c = 0; c < 64; c++) {
            float va0 = v0p[c];
            float va1 = v1p[c];
            float4 ea = *(const float4*)(ep + c * EP);  // 16B-aligned
            acc0[0] += va0 * ea.x; acc0[1] += va0 * ea.y;
            acc0[2] += va0 * ea.z; acc0[3] += va0 * ea.w;
            acc1[0] += va1 * ea.x; acc1[1] += va1 * ea.y;
            acc1[2] += va1 * ea.z; acc1[3] += va1 * ea.w;
        }
        __syncthreads();
    }

    // epilogue: dump sim tile, per-t argmax (first max, ascending l)
    {
        float* row0 = sim_s + (ti * 2 + 0) * 33 + li;
        float* row1 = sim_s + (ti * 2 + 1) * 33 + li;
#pragma unroll
        for (int j = 0; j < 4; j++) { row0[j] = acc0[j]; row1[j] = acc1[j]; }
    }
    __syncthreads();

    if (tid < 64) {
        const float* row = sim_s + tid * 33;
        float best = row[0]; int bl = 0;
#pragma unroll
        for (int l = 1; l < L; l++) {
            float v = row[l];
            if (v > best) { best = v; bl = l; }
        }
        g_labels[b * T + t0 + tid] = bl;
    }
}

// ---------------------------------------------------------------------------
// K4 (s-major, 8x store reuse, barrier-free, smem-free):
// val(b,s,c) = enc2[b, maj4(s), c] * sum4(vis[b, s..s+3, c])   (enc2 holds /4)
// out[b, s-4k, k, :] = val  for all valid k. Streaming stores.
// Per-warp autonomous: labels LDG'd broadcast (L1-hot), maj4 computed
// redundantly per lane. No BAR, no smem -> pure store stream.
// grid (ceil(NS/8), B) = 2048 blocks, 256 threads.
// ---------------------------------------------------------------------------
#define SBLK 8
__global__ void __launch_bounds__(256)
k_out(const float* __restrict__ vis, float* __restrict__ out) {
    const int b   = blockIdx.y;
    const int s0b = blockIdx.x * SBLK;
    const int tid = threadIdx.x;

    const int warp = tid >> 5, lane = tid & 31;
    const int half = warp & 1;            // which 512B half of the 1KB row
    const int j    = warp >> 1;           // s-pair 0..3
    const int coff = half * 32 + lane;    // float4 index within a row
    const int s    = s0b + j * 2;

    const bool v1 = (s + 1 < NS);
    if (s >= NS) return;

    // labels for maj4(s) and maj4(s+1): broadcast loads, L1-hot
    const int* labp = g_labels + b * T + s;
    int la0 = labp[0], la1 = labp[1], la2 = labp[2], la3 = labp[3];
    int la4 = v1 ? labp[4] : 0;
    const int l0 = maj4(la0, la1, la2, la3);
    const int l1 = v1 ? maj4(la1, la2, la3, la4) : 0;

    const float4* vcol = (const float4*)(vis + ((size_t)b * T) * C) + coff;
    const float4* encb = (const float4*)(g_enc2 + (size_t)b * L * C) + coff;
    float4* outb = (float4*)out + (size_t)b * NW * (NCH * 64) + coff;

    // issue all global loads up-front (MLP 7)
    float4 r0 = vcol[(size_t)(s + 0) * 64];
    float4 r1 = vcol[(size_t)(s + 1) * 64];
    float4 r2 = vcol[(size_t)(s + 2) * 64];
    float4 r3 = vcol[(size_t)(s + 3) * 64];
    float4 r4 = v1 ? vcol[(size_t)(s + 4) * 64] : make_float4(0.f, 0.f, 0.f, 0.f);
    float4 e0 = encb[(size_t)l0 * 64];
    float4 e1 = v1 ? encb[(size_t)l1 * 64] : make_float4(0.f, 0.f, 0.f, 0.f);

    // window s
    {
        float4 val = make_float4((r0.x + r1.x + r2.x + r3.x) * e0.x,
                                 (r0.y + r1.y + r2.y + r3.y) * e0.y,
                                 (r0.z + r1.z + r2.z + r3.z) * e0.z,
                                 (r0.w + r1.w + r2.w + r3.w) * e0.w);
        const int kmax = (s >> 2) < 7 ? (s >> 2) : 7;
        const int kmin = (s <= NW - 1) ? 0 : ((s - (NW - 1) + 3) >> 2);
        float4* p = outb + ((size_t)(8 * s - 31 * kmin)) * 64;
        for (int k = kmin; k <= kmax; k++) {
            __stcs(p, val);
            p -= 31 * 64;
        }
    }
    // window s+1
    if (v1) {
        const int s1 = s + 1;
        float4 val = make_float4((r1.x + r2.x + r3.x + r4.x) * e1.x,
                                 (r1.y + r2.y + r3.y + r4.y) * e1.y,
                                 (r1.z + r2.z + r3.z + r4.z) * e1.z,
                                 (r1.w + r2.w + r3.w + r4.w) * e1.w);
        const int kmax = (s1 >> 2) < 7 ? (s1 >> 2) : 7;
        const int kmin = (s1 <= NW - 1) ? 0 : ((s1 - (NW - 1) + 3) >> 2);
        float4* p = outb + ((size_t)(8 * s1 - 31 * kmin)) * 64;
        for (int k = kmin; k <= kmax; k++) {
            __stcs(p, val);
            p -= 31 * 64;
        }
    }
}

// ---------------------------------------------------------------------------
extern "C" void kernel_launch(void* const* d_in, const int* in_sizes, int n_in,
                              void* d_out, int out_size) {
    const float* vis   = (const float*)d_in[0];  // (B,T,C)
    const float* query = (const float*)d_in[1];  // (B,L,DQ)
    const float* W1    = (const float*)d_in[2];  // (DQ,C)
    const float* b1    = (const float*)d_in[3];  // (C,)
    const float* W2    = (const float*)d_in[4];  // (DQ,C)
    const float* b2    = (const float*)d_in[5];  // (C,)
    float* out = (float*)d_out;

    (void)in_sizes; (void)n_in; (void)out_size;

    k_enc_partial<<<dim3(DSPLIT, B), 256>>>(query, W1, W2);
    k_enc_reduce<<<B * L, 256>>>(b1, b2);
    k_labels<<<dim3(T / 64, B), 256>>>(vis);
    k_out<<<dim3((NS + SBLK - 1) / SBLK, B), 256>>>(vis, out);
}

// round 14
// speedup vs baseline: 1.1551x; 1.1551x over previous
#include <cuda_runtime.h>
#include <cstdint>

// Problem constants
#define B   8
#define T   2048
#define C   256
#define L   32
#define DQ  512
#define WSZ 32
#define NCH 8
#define CIC 4
#define NW  2017      // T - WSZ + 1
#define NS  2045      // T - CIC + 1
#define DSPLIT 32     // d-split for enc partial GEMM (16 d per chunk)
#define DCH (DQ / DSPLIT)   // 16

// ---------------- scratch (device globals; no allocs allowed) ----------------
__device__ float g_part1[DSPLIT * B * L * C];   // 8 MB
__device__ float g_part2[DSPLIT * B * L * C];   // 8 MB
__device__ float g_enc1[B * L * C];             // 256 KB
__device__ float g_enc2[B * L * C];             // 256 KB (pre-scaled by 0.25)
__device__ int   g_labels[B * T];               // 64 KB

// majority of 4 labels; tie -> smallest label (== argmax-first over counts)
__device__ __forceinline__ int maj4(int a0, int a1, int a2, int a3) {
    int la[4] = {a0, a1, a2, a3};
    int bc = 0, bl = L;
#pragma unroll
    for (int i = 0; i < 4; i++) {
        int cnt = (la[0] == la[i]) + (la[1] == la[i]) +
                  (la[2] == la[i]) + (la[3] == la[i]);
        if (cnt > bc || (cnt == bc && la[i] < bl)) { bc = cnt; bl = la[i]; }
    }
    return bl;
}

// ---------------------------------------------------------------------------
// K1a: partial enc GEMMs.  enc{1,2}[b,l,c] = sum_d query[b,l,d]*W{1,2}[d,c]
// grid (DSPLIT, B) = 256 blocks, 256 threads. 16 d per chunk.
// ---------------------------------------------------------------------------
__global__ void k_enc_partial(const float* __restrict__ query,
                              const float* __restrict__ W1,
                              const float* __restrict__ W2) {
    __shared__ float q_s[L * DCH];   // [l][dd]
    const int b  = blockIdx.y;
    const int dc = blockIdx.x;
    const int d0 = dc * DCH;

    for (int i = threadIdx.x; i < L * DCH; i += 256) {
        int l = i / DCH, dd = i % DCH;
        q_s[i] = query[((b * L + l) * DQ) + d0 + dd];
    }
    __syncthreads();

    const int warp = threadIdx.x >> 5, lane = threadIdx.x & 31;

    float4 a1[4][2], a2[4][2];
#pragma unroll
    for (int i = 0; i < 4; i++)
#pragma unroll
        for (int p = 0; p < 2; p++) {
            a1[i][p] = make_float4(0.f, 0.f, 0.f, 0.f);
            a2[i][p] = make_float4(0.f, 0.f, 0.f, 0.f);
        }

#pragma unroll 4
    for (int dd = 0; dd < DCH; dd++) {
        const int d = d0 + dd;
        const float4* w1r = (const float4*)(W1 + d * C);
        const float4* w2r = (const float4*)(W2 + d * C);
        float4 w1a = w1r[lane], w1b = w1r[lane + 32];
        float4 w2a = w2r[lane], w2b = w2r[lane + 32];
#pragma unroll
        for (int i = 0; i < 4; i++) {
            float q = q_s[(warp * 4 + i) * DCH + dd];
            a1[i][0].x += q * w1a.x; a1[i][0].y += q * w1a.y;
            a1[i][0].z += q * w1a.z; a1[i][0].w += q * w1a.w;
            a1[i][1].x += q * w1b.x; a1[i][1].y += q * w1b.y;
            a1[i][1].z += q * w1b.z; a1[i][1].w += q * w1b.w;
            a2[i][0].x += q * w2a.x; a2[i][0].y += q * w2a.y;
            a2[i][0].z += q * w2a.z; a2[i][0].w += q * w2a.w;
            a2[i][1].x += q * w2b.x; a2[i][1].y += q * w2b.y;
            a2[i][1].z += q * w2b.z; a2[i][1].w += q * w2b.w;
        }
    }

#pragma unroll
    for (int i = 0; i < 4; i++) {
        int l = warp * 4 + i;
        float4* p1 = (float4*)(g_part1 + (((size_t)dc * B + b) * L + l) * C);
        float4* p2 = (float4*)(g_part2 + (((size_t)dc * B + b) * L + l) * C);
        p1[lane] = a1[i][0]; p1[lane + 32] = a1[i][1];
        p2[lane] = a2[i][0]; p2[lane + 32] = a2[i][1];
    }
}

// K1b: reduce d-split partials + bias. grid (B*L), 256 threads (thread = c).
// NOTE: g_enc2 is pre-scaled by 0.25 (the mean4 divisor) — exact pow2 scale.
__global__ void k_enc_reduce(const float* __restrict__ b1,
                             const float* __restrict__ b2) {
    const int b = blockIdx.x >> 5, l = blockIdx.x & 31, c = threadIdx.x;
    float s1 = 0.f, s2 = 0.f;
#pragma unroll
    for (int dc = 0; dc < DSPLIT; dc++) {
        size_t idx = (((size_t)dc * B + b) * L + l) * C + c;
        s1 += g_part1[idx];
        s2 += g_part2[idx];
    }
    g_enc1[(b * L + l) * C + c] = s1 + b1[c];
    g_enc2[(b * L + l) * C + c] = 0.25f * (s2 + b2[c]);
}

// ---------------------------------------------------------------------------
// K2 (GEMM-tiled, shuffle-free — R10 shape, measured best):
// sim[t,l] = sum_c vis[b,t,c]*enc1[b,l,c];  labels[b,t] = argmax_l (first max).
// Block = 128 thr, tile 64t x 32l; thread = 4t x 4l (ILP 16).
// enc1 staged transposed [c][l] (stride 36); vis staged [t][c] stride 65.
// grid (T/64, B) = 256 blocks.
// ---------------------------------------------------------------------------
#define VP 65
#define EP 36
__global__ void __launch_bounds__(128)
k_labels(const float* __restrict__ vis) {
    __shared__ float vis_s[64 * VP];    // 16.6 KB
    __shared__ float enc_s[64 * EP];    //  9.2 KB
    __shared__ float sim_s[64 * 33];    //  8.4 KB

    const int b  = blockIdx.y;
    const int t0 = blockIdx.x * 64;
    const int tid = threadIdx.x;
    const int ti = tid >> 3;          // 0..15 -> t rows ti*4..+3
    const int li = (tid & 7) * 4;     // 0,4,...,28

    float acc[4][4];
#pragma unroll
    for (int i = 0; i < 4; i++)
#pragma unroll
        for (int j = 0; j < 4; j++) acc[i][j] = 0.f;

    for (int ch = 0; ch < 4; ch++) {
#pragma unroll
        for (int k = 0; k < 8; k++) {
            int slot = tid + k * 128;
            int r = slot >> 4, c4 = slot & 15;
            float4 vv = *((const float4*)(vis + ((size_t)(b * T + t0 + r)) * C + ch * 64) + c4);
            float* dst = vis_s + r * VP + c4 * 4;
            dst[0] = vv.x; dst[1] = vv.y; dst[2] = vv.z; dst[3] = vv.w;
        }
#pragma unroll
        for (int k = 0; k < 4; k++) {
            int slot = tid + k * 128;
            int l = slot >> 4, c4 = slot & 15;
            float4 ev = *((const float4*)(g_enc1 + (size_t)(b * L + l) * C + ch * 64) + c4);
            enc_s[(c4 * 4 + 0) * EP + l] = ev.x;
            enc_s[(c4 * 4 + 1) * EP + l] = ev.y;
            enc_s[(c4 * 4 + 2) * EP + l] = ev.z;
            enc_s[(c4 * 4 + 3) * EP + l] = ev.w;
        }
        __syncthreads();

#pragma unroll 4
        for (int c = 0; c < 64; c++) {
            float va0 = vis_s[(ti * 4 + 0) * VP + c];
            float va1 = vis_s[(ti * 4 + 1) * VP + c];
            float va2 = vis_s[(ti * 4 + 2) * VP + c];
            float va3 = vis_s[(ti * 4 + 3) * VP + c];
            float4 ea = *(const float4*)(enc_s + c * EP + li);
            acc[0][0] += va0 * ea.x; acc[0][1] += va0 * ea.y;
            acc[0][2] += va0 * ea.z; acc[0][3] += va0 * ea.w;
            acc[1][0] += va1 * ea.x; acc[1][1] += va1 * ea.y;
            acc[1][2] += va1 * ea.z; acc[1][3] += va1 * ea.w;
            acc[2][0] += va2 * ea.x; acc[2][1] += va2 * ea.y;
            acc[2][2] += va2 * ea.z; acc[2][3] += va2 * ea.w;
            acc[3][0] += va3 * ea.x; acc[3][1] += va3 * ea.y;
            acc[3][2] += va3 * ea.z; acc[3][3] += va3 * ea.w;
        }
        __syncthreads();
    }

#pragma unroll
    for (int i = 0; i < 4; i++)
#pragma unroll
        for (int j = 0; j < 4; j++)
            sim_s[(ti * 4 + i) * 33 + li + j] = acc[i][j];
    __syncthreads();

    if (tid < 64) {
        const float* row = sim_s + tid * 33;
        float best = row[0]; int bl = 0;
#pragma unroll
        for (int l = 1; l < L; l++) {
            float v = row[l];
            if (v > best) { best = v; bl = l; }
        }
        g_labels[b * T + t0 + tid] = bl;
    }
}

// ---------------------------------------------------------------------------
// K4 (s-major, 8x store reuse, barrier-free, smem-free — R13, measured equal):
// val(b,s,c) = enc2[b, maj4(s), c] * sum4(vis[b, s..s+3, c])   (enc2 holds /4)
// out[b, s-4k, k, :] = val  for all valid k. Streaming stores.
// grid (ceil(NS/8), B) = 2048 blocks, 256 threads.
// ---------------------------------------------------------------------------
#define SBLK 8
__global__ void __launch_bounds__(256)
k_out(const float* __restrict__ vis, float* __restrict__ out) {
    const int b   = blockIdx.y;
    const int s0b = blockIdx.x * SBLK;
    const int tid = threadIdx.x;

    const int warp = tid >> 5, lane = tid & 31;
    const int half = warp & 1;            // which 512B half of the 1KB row
    const int j    = warp >> 1;           // s-pair 0..3
    const int coff = half * 32 + lane;    // float4 index within a row
    const int s    = s0b + j * 2;

    const bool v1 = (s + 1 < NS);
    if (s >= NS) return;

    // labels for maj4(s) and maj4(s+1): broadcast loads, L1-hot
    const int* labp = g_labels + b * T + s;
    int la0 = labp[0], la1 = labp[1], la2 = labp[2], la3 = labp[3];
    int la4 = v1 ? labp[4] : 0;
    const int l0 = maj4(la0, la1, la2, la3);
    const int l1 = v1 ? maj4(la1, la2, la3, la4) : 0;

    const float4* vcol = (const float4*)(vis + ((size_t)b * T) * C) + coff;
    const float4* encb = (const float4*)(g_enc2 + (size_t)b * L * C) + coff;
    float4* outb = (float4*)out + (size_t)b * NW * (NCH * 64) + coff;

    // issue all global loads up-front (MLP 7)
    float4 r0 = vcol[(size_t)(s + 0) * 64];
    float4 r1 = vcol[(size_t)(s + 1) * 64];
    float4 r2 = vcol[(size_t)(s + 2) * 64];
    float4 r3 = vcol[(size_t)(s + 3) * 64];
    float4 r4 = v1 ? vcol[(size_t)(s + 4) * 64] : make_float4(0.f, 0.f, 0.f, 0.f);
    float4 e0 = encb[(size_t)l0 * 64];
    float4 e1 = v1 ? encb[(size_t)l1 * 64] : make_float4(0.f, 0.f, 0.f, 0.f);

    // window s
    {
        float4 val = make_float4((r0.x + r1.x + r2.x + r3.x) * e0.x,
                                 (r0.y + r1.y + r2.y + r3.y) * e0.y,
                                 (r0.z + r1.z + r2.z + r3.z) * e0.z,
                                 (r0.w + r1.w + r2.w + r3.w) * e0.w);
        const int kmax = (s >> 2) < 7 ? (s >> 2) : 7;
        const int kmin = (s <= NW - 1) ? 0 : ((s - (NW - 1) + 3) >> 2);
        float4* p = outb + ((size_t)(8 * s - 31 * kmin)) * 64;
        for (int k = kmin; k <= kmax; k++) {
            __stcs(p, val);
            p -= 31 * 64;
        }
    }
    // window s+1
    if (v1) {
        const int s1 = s + 1;
        float4 val = make_float4((r1.x + r2.x + r3.x + r4.x) * e1.x,
                                 (r1.y + r2.y + r3.y + r4.y) * e1.y,
                                 (r1.z + r2.z + r3.z + r4.z) * e1.z,
                                 (r1.w + r2.w + r3.w + r4.w) * e1.w);
        const int kmax = (s1 >> 2) < 7 ? (s1 >> 2) : 7;
        const int kmin = (s1 <= NW - 1) ? 0 : ((s1 - (NW - 1) + 3) >> 2);
        float4* p = outb + ((size_t)(8 * s1 - 31 * kmin)) * 64;
        for (int k = kmin; k <= kmax; k++) {
            __stcs(p, val);
            p -= 31 * 64;
        }
    }
}

// ---------------------------------------------------------------------------
extern "C" void kernel_launch(void* const* d_in, const int* in_sizes, int n_in,
                              void* d_out, int out_size) {
    const float* vis   = (const float*)d_in[0];  // (B,T,C)
    const float* query = (const float*)d_in[1];  // (B,L,DQ)
    const float* W1    = (const float*)d_in[2];  // (DQ,C)
    const float* b1    = (const float*)d_in[3];  // (C,)
    const float* W2    = (const float*)d_in[4];  // (DQ,C)
    const float* b2    = (const float*)d_in[5];  // (C,)
    float* out = (float*)d_out;

    (void)in_sizes; (void)n_in; (void)out_size;

    k_enc_partial<<<dim3(DSPLIT, B), 256>>>(query, W1, W2);
    k_enc_reduce<<<B * L, 256>>>(b1, b2);
    k_labels<<<dim3(T / 64, B), 128>>>(vis);
    k_out<<<dim3((NS + SBLK - 1) / SBLK, B), 256>>>(vis, out);
}

// round 15
// speedup vs baseline: 1.1621x; 1.0060x over previous
#include <cuda_runtime.h>
#include <cstdint>

// Problem constants
#define B   8
#define T   2048
#define C   256
#define L   32
#define DQ  512
#define WSZ 32
#define NCH 8
#define CIC 4
#define NW  2017      // T - WSZ + 1
#define NS  2045      // T - CIC + 1
#define DSPLIT 32     // d-split for enc partial GEMM (16 d per chunk)
#define DCH (DQ / DSPLIT)   // 16

// ---------------- scratch (device globals; no allocs allowed) ----------------
__device__ float g_part1[DSPLIT * B * L * C];   // 8 MB
__device__ float g_part2[DSPLIT * B * L * C];   // 8 MB
__device__ float g_enc1[B * L * C];             // 256 KB
__device__ float g_enc2[B * L * C];             // 256 KB (pre-scaled by 0.25)
__device__ int   g_labels[B * T];               // 64 KB

// majority of 4 labels; tie -> smallest label (== argmax-first over counts)
__device__ __forceinline__ int maj4(int a0, int a1, int a2, int a3) {
    int la[4] = {a0, a1, a2, a3};
    int bc = 0, bl = L;
#pragma unroll
    for (int i = 0; i < 4; i++) {
        int cnt = (la[0] == la[i]) + (la[1] == la[i]) +
                  (la[2] == la[i]) + (la[3] == la[i]);
        if (cnt > bc || (cnt == bc && la[i] < bl)) { bc = cnt; bl = la[i]; }
    }
    return bl;
}

// ---------------------------------------------------------------------------
// K1a: partial enc GEMMs.  enc{1,2}[b,l,c] = sum_d query[b,l,d]*W{1,2}[d,c]
// grid (DSPLIT, B) = 256 blocks, 256 threads. 16 d per chunk.
// ---------------------------------------------------------------------------
__global__ void k_enc_partial(const float* __restrict__ query,
                              const float* __restrict__ W1,
                              const float* __restrict__ W2) {
    __shared__ float q_s[L * DCH];   // [l][dd]
    const int b  = blockIdx.y;
    const int dc = blockIdx.x;
    const int d0 = dc * DCH;

    for (int i = threadIdx.x; i < L * DCH; i += 256) {
        int l = i / DCH, dd = i % DCH;
        q_s[i] = query[((b * L + l) * DQ) + d0 + dd];
    }
    __syncthreads();

    const int warp = threadIdx.x >> 5, lane = threadIdx.x & 31;

    float4 a1[4][2], a2[4][2];
#pragma unroll
    for (int i = 0; i < 4; i++)
#pragma unroll
        for (int p = 0; p < 2; p++) {
            a1[i][p] = make_float4(0.f, 0.f, 0.f, 0.f);
            a2[i][p] = make_float4(0.f, 0.f, 0.f, 0.f);
        }

#pragma unroll 4
    for (int dd = 0; dd < DCH; dd++) {
        const int d = d0 + dd;
        const float4* w1r = (const float4*)(W1 + d * C);
        const float4* w2r = (const float4*)(W2 + d * C);
        float4 w1a = w1r[lane], w1b = w1r[lane + 32];
        float4 w2a = w2r[lane], w2b = w2r[lane + 32];
#pragma unroll
        for (int i = 0; i < 4; i++) {
            float q = q_s[(warp * 4 + i) * DCH + dd];
            a1[i][0].x += q * w1a.x; a1[i][0].y += q * w1a.y;
            a1[i][0].z += q * w1a.z; a1[i][0].w += q * w1a.w;
            a1[i][1].x += q * w1b.x; a1[i][1].y += q * w1b.y;
            a1[i][1].z += q * w1b.z; a1[i][1].w += q * w1b.w;
            a2[i][0].x += q * w2a.x; a2[i][0].y += q * w2a.y;
            a2[i][0].z += q * w2a.z; a2[i][0].w += q * w2a.w;
            a2[i][1].x += q * w2b.x; a2[i][1].y += q * w2b.y;
            a2[i][1].z += q * w2b.z; a2[i][1].w += q * w2b.w;
        }
    }

#pragma unroll
    for (int i = 0; i < 4; i++) {
        int l = warp * 4 + i;
        float4* p1 = (float4*)(g_part1 + (((size_t)dc * B + b) * L + l) * C);
        float4* p2 = (float4*)(g_part2 + (((size_t)dc * B + b) * L + l) * C);
        p1[lane] = a1[i][0]; p1[lane + 32] = a1[i][1];
        p2[lane] = a2[i][0]; p2[lane + 32] = a2[i][1];
    }
}

// K1b: reduce d-split partials + bias. grid (B*L), 256 threads (thread = c).
// PDL: sync before reading partials. g_enc2 pre-scaled by 0.25 (exact pow2).
__global__ void k_enc_reduce(const float* __restrict__ b1,
                             const float* __restrict__ b2) {
    const int b = blockIdx.x >> 5, l = blockIdx.x & 31, c = threadIdx.x;
    float bias1 = b1[c], bias2 = b2[c];        // inputs: no dependency
    cudaGridDependencySynchronize();           // wait for k_enc_partial
    float s1 = 0.f, s2 = 0.f;
#pragma unroll
    for (int dc = 0; dc < DSPLIT; dc++) {
        size_t idx = (((size_t)dc * B + b) * L + l) * C + c;
        s1 += g_part1[idx];
        s2 += g_part2[idx];
    }
    g_enc1[(b * L + l) * C + c] = s1 + bias1;
    g_enc2[(b * L + l) * C + c] = 0.25f * (s2 + bias2);
}

// ---------------------------------------------------------------------------
// K2 (GEMM-tiled, shuffle-free, PDL-prefetched):
// sim[t,l] = sum_c vis[b,t,c]*enc1[b,l,c];  labels[b,t] = argmax_l (first max).
// Block = 128 thr, tile 64t x 32l; thread = 4t x 4l (ILP 16).
// PDL: vis chunk-0 staged BEFORE grid-dependency sync (vis is enc-independent)
// -> overlaps k_enc_reduce tail. enc1 reads only after sync.
// grid (T/64, B) = 256 blocks.
// ---------------------------------------------------------------------------
#define VP 65
#define EP 36
__global__ void __launch_bounds__(128)
k_labels(const float* __restrict__ vis) {
    __shared__ float vis_s[64 * VP];    // 16.6 KB
    __shared__ float enc_s[64 * EP];    //  9.2 KB
    __shared__ float sim_s[64 * 33];    //  8.4 KB

    const int b  = blockIdx.y;
    const int t0 = blockIdx.x * 64;
    const int tid = threadIdx.x;
    const int ti = tid >> 3;          // 0..15 -> t rows ti*4..+3
    const int li = (tid & 7) * 4;     // 0,4,...,28

    float acc[4][4];
#pragma unroll
    for (int i = 0; i < 4; i++)
#pragma unroll
        for (int j = 0; j < 4; j++) acc[i][j] = 0.f;

    // pre-sync: stage vis chunk 0 (no dependency on enc1)
#pragma unroll
    for (int k = 0; k < 8; k++) {
        int slot = tid + k * 128;
        int r = slot >> 4, c4 = slot & 15;
        float4 vv = *((const float4*)(vis + ((size_t)(b * T + t0 + r)) * C) + c4);
        float* dst = vis_s + r * VP + c4 * 4;
        dst[0] = vv.x; dst[1] = vv.y; dst[2] = vv.z; dst[3] = vv.w;
    }

    cudaGridDependencySynchronize();   // wait for k_enc_reduce (g_enc1)

    for (int ch = 0; ch < 4; ch++) {
        if (ch > 0) {
            // stage vis rows t0..+63, cols ch*64..+63 (1024 float4 slots)
#pragma unroll
            for (int k = 0; k < 8; k++) {
                int slot = tid + k * 128;
                int r = slot >> 4, c4 = slot & 15;
                float4 vv = *((const float4*)(vis + ((size_t)(b * T + t0 + r)) * C + ch * 64) + c4);
                float* dst = vis_s + r * VP + c4 * 4;
                dst[0] = vv.x; dst[1] = vv.y; dst[2] = vv.z; dst[3] = vv.w;
            }
        }
        // stage enc1 transposed [c][l] (512 float4 slots)
#pragma unroll
        for (int k = 0; k < 4; k++) {
            int slot = tid + k * 128;
            int l = slot >> 4, c4 = slot & 15;
            float4 ev = *((const float4*)(g_enc1 + (size_t)(b * L + l) * C + ch * 64) + c4);
            enc_s[(c4 * 4 + 0) * EP + l] = ev.x;
            enc_s[(c4 * 4 + 1) * EP + l] = ev.y;
            enc_s[(c4 * 4 + 2) * EP + l] = ev.z;
            enc_s[(c4 * 4 + 3) * EP + l] = ev.w;
        }
        __syncthreads();

#pragma unroll 4
        for (int c = 0; c < 64; c++) {
            float va0 = vis_s[(ti * 4 + 0) * VP + c];
            float va1 = vis_s[(ti * 4 + 1) * VP + c];
            float va2 = vis_s[(ti * 4 + 2) * VP + c];
            float va3 = vis_s[(ti * 4 + 3) * VP + c];
            float4 ea = *(const float4*)(enc_s + c * EP + li);
            acc[0][0] += va0 * ea.x; acc[0][1] += va0 * ea.y;
            acc[0][2] += va0 * ea.z; acc[0][3] += va0 * ea.w;
            acc[1][0] += va1 * ea.x; acc[1][1] += va1 * ea.y;
            acc[1][2] += va1 * ea.z; acc[1][3] += va1 * ea.w;
            acc[2][0] += va2 * ea.x; acc[2][1] += va2 * ea.y;
            acc[2][2] += va2 * ea.z; acc[2][3] += va2 * ea.w;
            acc[3][0] += va3 * ea.x; acc[3][1] += va3 * ea.y;
            acc[3][2] += va3 * ea.z; acc[3][3] += va3 * ea.w;
        }
        __syncthreads();
    }

#pragma unroll
    for (int i = 0; i < 4; i++)
#pragma unroll
        for (int j = 0; j < 4; j++)
            sim_s[(ti * 4 + i) * 33 + li + j] = acc[i][j];
    __syncthreads();

    if (tid < 64) {
        const float* row = sim_s + tid * 33;
        float best = row[0]; int bl = 0;
#pragma unroll
        for (int l = 1; l < L; l++) {
            float v = row[l];
            if (v > best) { best = v; bl = l; }
        }
        g_labels[b * T + t0 + tid] = bl;
    }
}

// ---------------------------------------------------------------------------
// K4 (s-major, 8x store reuse, barrier-free, PDL-prefetched):
// val(b,s,c) = enc2[b, maj4(s), c] * sum4(vis[b, s..s+3, c])   (enc2 holds /4)
// out[b, s-4k, k, :] = val  for all valid k. Streaming stores.
// PDL: all 5 vis LDG.128 issued BEFORE grid-dependency sync (vis independent
// of labels) -> prefetch latency overlaps k_labels tail. labels/enc2 after.
// grid (ceil(NS/8), B) = 2048 blocks, 256 threads.
// ---------------------------------------------------------------------------
#define SBLK 8
__global__ void __launch_bounds__(256)
k_out(const float* __restrict__ vis, float* __restrict__ out) {
    const int b   = blockIdx.y;
    const int s0b = blockIdx.x * SBLK;
    const int tid = threadIdx.x;

    const int warp = tid >> 5, lane = tid & 31;
    const int half = warp & 1;            // which 512B half of the 1KB row
    const int j    = warp >> 1;           // s-pair 0..3
    const int coff = half * 32 + lane;    // float4 index within a row
    const int s    = s0b + j * 2;

    const bool v1 = (s + 1 < NS);
    if (s >= NS) {
        cudaGridDependencySynchronize();
        return;
    }

    const float4* vcol = (const float4*)(vis + ((size_t)b * T) * C) + coff;
    const float4* encb = (const float4*)(g_enc2 + (size_t)b * L * C) + coff;
    float4* outb = (float4*)out + (size_t)b * NW * (NCH * 64) + coff;

    // pre-sync: issue all vis loads (MLP 5), independent of labels
    float4 r0 = vcol[(size_t)(s + 0) * 64];
    float4 r1 = vcol[(size_t)(s + 1) * 64];
    float4 r2 = vcol[(size_t)(s + 2) * 64];
    float4 r3 = vcol[(size_t)(s + 3) * 64];
    float4 r4 = v1 ? vcol[(size_t)(s + 4) * 64] : make_float4(0.f, 0.f, 0.f, 0.f);

    cudaGridDependencySynchronize();   // wait for k_labels (g_labels)

    // labels for maj4(s) and maj4(s+1): broadcast loads, L1-hot
    const int* labp = g_labels + b * T + s;
    int la0 = labp[0], la1 = labp[1], la2 = labp[2], la3 = labp[3];
    int la4 = v1 ? labp[4] : 0;
    const int l0 = maj4(la0, la1, la2, la3);
    const int l1 = v1 ? maj4(la1, la2, la3, la4) : 0;

    float4 e0 = encb[(size_t)l0 * 64];
    float4 e1 = v1 ? encb[(size_t)l1 * 64] : make_float4(0.f, 0.f, 0.f, 0.f);

    // window s
    {
        float4 val = make_float4((r0.x + r1.x + r2.x + r3.x) * e0.x,
                                 (r0.y + r1.y + r2.y + r3.y) * e0.y,
                                 (r0.z + r1.z + r2.z + r3.z) * e0.z,
                                 (r0.w + r1.w + r2.w + r3.w) * e0.w);
        const int kmax = (s >> 2) < 7 ? (s >> 2) : 7;
        const int kmin = (s <= NW - 1) ? 0 : ((s - (NW - 1) + 3) >> 2);
        float4* p = outb + ((size_t)(8 * s - 31 * kmin)) * 64;
        for (int k = kmin; k <= kmax; k++) {
            __stcs(p, val);
            p -= 31 * 64;
        }
    }
    // window s+1
    if (v1) {
        const int s1 = s + 1;
        float4 val = make_float4((r1.x + r2.x + r3.x + r4.x) * e1.x,
                                 (r1.y + r2.y + r3.y + r4.y) * e1.y,
                                 (r1.z + r2.z + r3.z + r4.z) * e1.z,
                                 (r1.w + r2.w + r3.w + r4.w) * e1.w);
        const int kmax = (s1 >> 2) < 7 ? (s1 >> 2) : 7;
        const int kmin = (s1 <= NW - 1) ? 0 : ((s1 - (NW - 1) + 3) >> 2);
        float4* p = outb + ((size_t)(8 * s1 - 31 * kmin)) * 64;
        for (int k = kmin; k <= kmax; k++) {
            __stcs(p, val);
            p -= 31 * 64;
        }
    }
}

// ---------------------------------------------------------------------------
// Launch: PDL chain. Each dependent kernel is launched with programmatic
// stream serialization and does its dependency-free prologue before
// cudaGridDependencySynchronize(). Falls back to serial semantics if the
// overlap window is empty. Graph-capturable (kernel launches only).
// ---------------------------------------------------------------------------
template <typename... Args>
static inline void launch_pdl(void (*kern)(Args...), dim3 grid, dim3 block,
                              Args... args) {
    cudaLaunchConfig_t cfg = {};
    cudaLaunchAttribute attr[1];
    attr[0].id = cudaLaunchAttributeProgrammaticStreamSerialization;
    attr[0].val.programmaticStreamSerializationAllowed = 1;
    cfg.gridDim = grid;
    cfg.blockDim = block;
    cfg.dynamicSmemBytes = 0;
    cfg.stream = 0;
    cfg.attrs = attr;
    cfg.numAttrs = 1;
    cudaLaunchKernelEx(&cfg, kern, args...);
}

extern "C" void kernel_launch(void* const* d_in, const int* in_sizes, int n_in,
                              void* d_out, int out_size) {
    const float* vis   = (const float*)d_in[0];  // (B,T,C)
    const float* query = (const float*)d_in[1];  // (B,L,DQ)
    const float* W1    = (const float*)d_in[2];  // (DQ,C)
    const float* b1    = (const float*)d_in[3];  // (C,)
    const float* W2    = (const float*)d_in[4];  // (DQ,C)
    const float* b2    = (const float*)d_in[5];  // (C,)
    float* out = (float*)d_out;

    (void)in_sizes; (void)n_in; (void)out_size;

    k_enc_partial<<<dim3(DSPLIT, B), 256>>>(query, W1, W2);
    launch_pdl(k_enc_reduce, dim3(B * L), dim3(256), b1, b2);
    launch_pdl(k_labels, dim3(T / 64, B), dim3(128), vis);
    launch_pdl(k_out, dim3((NS + SBLK - 1) / SBLK, B), dim3(256), vis, out);
}